// round 1
// baseline (speedup 1.0000x reference)
#include <cuda_runtime.h>
#include <math.h>

// Problem constants
#define BATCH 4
#define SEQ   2048
#define DIMC  1024
#define NHEAD 16
#define HDIM  64
#define MROWS (BATCH * SEQ)      // 8192
#define QK_SCALE 0.125f          // 64^-0.5

// Scratch (device globals — allocation-free per harness rules)
__device__ float g_q[(size_t)BATCH * NHEAD * SEQ * HDIM];
__device__ float g_k[(size_t)BATCH * NHEAD * SEQ * HDIM];
__device__ float g_v[(size_t)BATCH * NHEAD * SEQ * HDIM];
__device__ float g_attn[(size_t)MROWS * DIMC];

// ---------------------------------------------------------------------------
// Tiled SGEMM: C[M,N] = A[M,K] @ B[K,N] + bias[N]
// 64x64 block tile, K-tile 16, 256 threads, 4x4 per-thread microtile.
// MODE 0: epilogue scatters into g_q/g_k/g_v with [b*H+h][n][d] layout.
// MODE 1: A is g_attn (ignores A param), plain row-major store to C.
// ---------------------------------------------------------------------------
template <int MODE>
__global__ __launch_bounds__(256) void sgemm_k(
    const float* __restrict__ A, const float* __restrict__ B,
    const float* __restrict__ bias, float* __restrict__ C,
    int K, int Ncols)
{
    __shared__ float As[16][68];   // [k][m], padded, 16B-aligned rows
    __shared__ float Bs[16][68];   // [k][n], padded

    const float* __restrict__ Ap = (MODE == 0) ? A : g_attn;

    const int tid = threadIdx.x;
    const int m0 = blockIdx.y * 64;
    const int n0 = blockIdx.x * 64;
    const int ty = tid >> 4;       // 0..15
    const int tx = tid & 15;       // 0..15

    const int arow = tid >> 2;     // 0..63
    const int aseg = tid & 3;      // 0..3  (covers K-tile of 16 as 4x float4)
    const int brow = tid >> 4;     // 0..15
    const int bseg = tid & 15;     // 0..15 (covers 64 cols as 16x float4)

    float acc[4][4] = {};

    for (int k0 = 0; k0 < K; k0 += 16) {
        float4 av = *(const float4*)(Ap + (size_t)(m0 + arow) * K + k0 + aseg * 4);
        As[aseg * 4 + 0][arow] = av.x;
        As[aseg * 4 + 1][arow] = av.y;
        As[aseg * 4 + 2][arow] = av.z;
        As[aseg * 4 + 3][arow] = av.w;
        float4 bv = *(const float4*)(B + (size_t)(k0 + brow) * Ncols + n0 + bseg * 4);
        *(float4*)&Bs[brow][bseg * 4] = bv;
        __syncthreads();

#pragma unroll
        for (int kk = 0; kk < 16; kk++) {
            float4 a4 = *(const float4*)&As[kk][ty * 4];
            float4 b4 = *(const float4*)&Bs[kk][tx * 4];
            float ar[4] = {a4.x, a4.y, a4.z, a4.w};
            float br[4] = {b4.x, b4.y, b4.z, b4.w};
#pragma unroll
            for (int i = 0; i < 4; i++)
#pragma unroll
                for (int j = 0; j < 4; j++)
                    acc[i][j] += ar[i] * br[j];
        }
        __syncthreads();
    }

#pragma unroll
    for (int i = 0; i < 4; i++) {
        const int m = m0 + ty * 4 + i;
#pragma unroll
        for (int j = 0; j < 4; j++) {
            const int n = n0 + tx * 4 + j;
            float val = acc[i][j] + bias[n];
            if (MODE == 0) {
                // qkv col n -> (which, head, d); row m -> (b, s)
                const int which = n >> 10;          // / 1024
                const int h     = (n & 1023) >> 6;  // / 64
                const int d     = n & 63;
                const int b     = m >> 11;          // / 2048
                const int s     = m & 2047;
                float* dst = (which == 0) ? g_q : (which == 1) ? g_k : g_v;
                dst[(((size_t)(b * NHEAD + h)) * SEQ + s) * HDIM + d] = val;
            } else {
                C[(size_t)m * Ncols + n] = val;
            }
        }
    }
}

// ---------------------------------------------------------------------------
// Flash-style attention: per block one (bh, 32-row q-tile). Online softmax
// over K/V tiles of 32 rows. 256 threads: thread t owns q-row t/8, and for
// S an aligned 4-col slice, for O an aligned 8-col slice (HDIM=64).
// Writes g_attn in [b][s][h*64+d] layout (ready for proj GEMM).
// ---------------------------------------------------------------------------
__global__ __launch_bounds__(256) void attn_k()
{
    __shared__ float sQ [32][68];  // [row][d], pre-scaled
    __shared__ float sKT[64][33];  // [d][kcol] transposed, conflict-free S reads
    __shared__ float sV [32][68];  // [krow][d]
    __shared__ float sS [32][33];  // [qrow][kcol] probabilities

    const int tid = threadIdx.x;
    const int bh  = blockIdx.y;              // 0..63
    const int q0  = blockIdx.x * 32;

    const float* __restrict__ Qp = g_q + (size_t)bh * SEQ * HDIM;
    const float* __restrict__ Kp = g_k + (size_t)bh * SEQ * HDIM;
    const float* __restrict__ Vp = g_v + (size_t)bh * SEQ * HDIM;

    // Load + scale Q tile (32x64)
    for (int i = tid; i < (32 * HDIM) / 4; i += 256) {
        const int e = i * 4;
        const int r = e >> 6;
        const int d = e & 63;
        float4 qv = *(const float4*)(Qp + (size_t)(q0 + r) * HDIM + d);
        qv.x *= QK_SCALE; qv.y *= QK_SCALE; qv.z *= QK_SCALE; qv.w *= QK_SCALE;
        *(float4*)&sQ[r][d] = qv;
    }

    const int row = tid >> 3;        // q-row 0..31
    const int cb4 = (tid & 7) * 4;   // S col base
    const int cb8 = (tid & 7) * 8;   // O col base

    float acc[8] = {0, 0, 0, 0, 0, 0, 0, 0};
    float mrow = -1e30f;
    float lrow = 0.0f;

    for (int kt = 0; kt < SEQ / 32; kt++) {
        __syncthreads();   // protect sKT/sV from previous iteration's readers
        for (int i = tid; i < (32 * HDIM) / 4; i += 256) {
            const int e = i * 4;
            const int r = e >> 6;
            const int d = e & 63;
            float4 kv = *(const float4*)(Kp + (size_t)(kt * 32 + r) * HDIM + d);
            sKT[d + 0][r] = kv.x;
            sKT[d + 1][r] = kv.y;
            sKT[d + 2][r] = kv.z;
            sKT[d + 3][r] = kv.w;
            float4 vv = *(const float4*)(Vp + (size_t)(kt * 32 + r) * HDIM + d);
            *(float4*)&sV[r][d] = vv;
        }
        __syncthreads();

        // S = (Q*scale) @ K^T : 4 columns per thread
        float s0 = 0.f, s1 = 0.f, s2 = 0.f, s3 = 0.f;
#pragma unroll 8
        for (int d = 0; d < HDIM; d++) {
            const float q = sQ[row][d];
            s0 += q * sKT[d][cb4 + 0];
            s1 += q * sKT[d][cb4 + 1];
            s2 += q * sKT[d][cb4 + 2];
            s3 += q * sKT[d][cb4 + 3];
        }

        // row-wise max across the 8 lanes of this row (lanes aligned to 8)
        float tmax = fmaxf(fmaxf(s0, s1), fmaxf(s2, s3));
        tmax = fmaxf(tmax, __shfl_xor_sync(0xffffffffu, tmax, 1));
        tmax = fmaxf(tmax, __shfl_xor_sync(0xffffffffu, tmax, 2));
        tmax = fmaxf(tmax, __shfl_xor_sync(0xffffffffu, tmax, 4));

        const float newm = fmaxf(mrow, tmax);
        const float corr = __expf(mrow - newm);
        const float p0 = __expf(s0 - newm);
        const float p1 = __expf(s1 - newm);
        const float p2 = __expf(s2 - newm);
        const float p3 = __expf(s3 - newm);
        sS[row][cb4 + 0] = p0;
        sS[row][cb4 + 1] = p1;
        sS[row][cb4 + 2] = p2;
        sS[row][cb4 + 3] = p3;

        float ts = p0 + p1 + p2 + p3;
        ts += __shfl_xor_sync(0xffffffffu, ts, 1);
        ts += __shfl_xor_sync(0xffffffffu, ts, 2);
        ts += __shfl_xor_sync(0xffffffffu, ts, 4);

        lrow = lrow * corr + ts;
        mrow = newm;
#pragma unroll
        for (int c = 0; c < 8; c++) acc[c] *= corr;

        __syncwarp();   // sS written and read within the same warp

        // O += P @ V (8 cols per thread, float4 smem reads w/ broadcast)
#pragma unroll 4
        for (int kk = 0; kk < 32; kk++) {
            const float p = sS[row][kk];
            const float4 va = *(const float4*)&sV[kk][cb8];
            const float4 vb = *(const float4*)&sV[kk][cb8 + 4];
            acc[0] += p * va.x; acc[1] += p * va.y;
            acc[2] += p * va.z; acc[3] += p * va.w;
            acc[4] += p * vb.x; acc[5] += p * vb.y;
            acc[6] += p * vb.z; acc[7] += p * vb.w;
        }
    }

    const float inv = 1.0f / lrow;
    const int b = bh >> 4;
    const int h = bh & 15;
    float* op = g_attn + ((size_t)(b * SEQ + q0 + row)) * DIMC + h * HDIM + cb8;
#pragma unroll
    for (int c = 0; c < 8; c++) op[c] = acc[c] * inv;
}

// ---------------------------------------------------------------------------
extern "C" void kernel_launch(void* const* d_in, const int* in_sizes, int n_in,
                              void* d_out, int out_size)
{
    const float* x      = (const float*)d_in[0];
    const float* w_qkv  = (const float*)d_in[1];
    const float* b_qkv  = (const float*)d_in[2];
    const float* w_proj = (const float*)d_in[3];
    const float* b_proj = (const float*)d_in[4];
    float* out = (float*)d_out;

    // 1) qkv = x @ w_qkv + b_qkv, scattered into g_q/g_k/g_v [bh][s][d]
    {
        dim3 grid(3 * DIMC / 64, MROWS / 64);   // (48, 128)
        sgemm_k<0><<<grid, 256>>>(x, w_qkv, b_qkv, nullptr, DIMC, 3 * DIMC);
    }
    // 2) attention -> g_attn [b][s][h*64+d]
    {
        dim3 grid(SEQ / 32, BATCH * NHEAD);     // (64, 64)
        attn_k<<<grid, 256>>>();
    }
    // 3) out = g_attn @ w_proj + b_proj
    {
        dim3 grid(DIMC / 64, MROWS / 64);       // (16, 128)
        sgemm_k<1><<<grid, 256>>>(nullptr, w_proj, b_proj, out, DIMC, DIMC);
    }
}

// round 2
// speedup vs baseline: 1.0000x; 1.0000x over previous
#include <cuda_runtime.h>
#include <math.h>

// Problem constants
#define BATCH 4
#define SEQ   2048
#define DIMC  1024
#define NHEAD 16
#define HDIM  64
#define MROWS (BATCH * SEQ)      // 8192
#define QK_SCALE 0.125f          // 64^-0.5

// Scratch (device globals — allocation-free per harness rules)
__device__ float g_q[(size_t)BATCH * NHEAD * SEQ * HDIM];
__device__ float g_k[(size_t)BATCH * NHEAD * SEQ * HDIM];
__device__ float g_v[(size_t)BATCH * NHEAD * SEQ * HDIM];
__device__ float g_attn[(size_t)MROWS * DIMC];

// ---------------------------------------------------------------------------
// Tiled SGEMM: C[M,N] = A[M,K] @ B[K,N] + bias[N]
// 64x64 block tile, K-tile 16, 256 threads, 4x4 per-thread microtile.
// MODE 0: epilogue scatters into g_q/g_k/g_v with [b*H+h][n][d] layout.
// MODE 1: A is g_attn (ignores A param), plain row-major store to C.
// ---------------------------------------------------------------------------
template <int MODE>
__global__ __launch_bounds__(256) void sgemm_k(
    const float* __restrict__ A, const float* __restrict__ B,
    const float* __restrict__ bias, float* __restrict__ C,
    int K, int Ncols)
{
    __shared__ float As[16][68];   // [k][m], padded, 16B-aligned rows
    __shared__ float Bs[16][68];   // [k][n], padded

    const float* __restrict__ Ap = (MODE == 0) ? A : g_attn;

    const int tid = threadIdx.x;
    const int m0 = blockIdx.y * 64;
    const int n0 = blockIdx.x * 64;
    const int ty = tid >> 4;       // 0..15
    const int tx = tid & 15;       // 0..15

    const int arow = tid >> 2;     // 0..63
    const int aseg = tid & 3;      // 0..3  (covers K-tile of 16 as 4x float4)
    const int brow = tid >> 4;     // 0..15
    const int bseg = tid & 15;     // 0..15 (covers 64 cols as 16x float4)

    float acc[4][4] = {};

    for (int k0 = 0; k0 < K; k0 += 16) {
        float4 av = *(const float4*)(Ap + (size_t)(m0 + arow) * K + k0 + aseg * 4);
        As[aseg * 4 + 0][arow] = av.x;
        As[aseg * 4 + 1][arow] = av.y;
        As[aseg * 4 + 2][arow] = av.z;
        As[aseg * 4 + 3][arow] = av.w;
        float4 bv = *(const float4*)(B + (size_t)(k0 + brow) * Ncols + n0 + bseg * 4);
        *(float4*)&Bs[brow][bseg * 4] = bv;
        __syncthreads();

#pragma unroll
        for (int kk = 0; kk < 16; kk++) {
            float4 a4 = *(const float4*)&As[kk][ty * 4];
            float4 b4 = *(const float4*)&Bs[kk][tx * 4];
            float ar[4] = {a4.x, a4.y, a4.z, a4.w};
            float br[4] = {b4.x, b4.y, b4.z, b4.w};
#pragma unroll
            for (int i = 0; i < 4; i++)
#pragma unroll
                for (int j = 0; j < 4; j++)
                    acc[i][j] += ar[i] * br[j];
        }
        __syncthreads();
    }

#pragma unroll
    for (int i = 0; i < 4; i++) {
        const int m = m0 + ty * 4 + i;
#pragma unroll
        for (int j = 0; j < 4; j++) {
            const int n = n0 + tx * 4 + j;
            float val = acc[i][j] + bias[n];
            if (MODE == 0) {
                // qkv col n -> (which, head, d); row m -> (b, s)
                const int which = n >> 10;          // / 1024
                const int h     = (n & 1023) >> 6;  // / 64
                const int d     = n & 63;
                const int b     = m >> 11;          // / 2048
                const int s     = m & 2047;
                float* dst = (which == 0) ? g_q : (which == 1) ? g_k : g_v;
                dst[(((size_t)(b * NHEAD + h)) * SEQ + s) * HDIM + d] = val;
            } else {
                C[(size_t)m * Ncols + n] = val;
            }
        }
    }
}

// ---------------------------------------------------------------------------
// Flash-style attention: per block one (bh, 32-row q-tile). Online softmax
// over K/V tiles of 32 rows. 256 threads: thread t owns q-row t/8, and for
// S an aligned 4-col slice, for O an aligned 8-col slice (HDIM=64).
// Writes g_attn in [b][s][h*64+d] layout (ready for proj GEMM).
// ---------------------------------------------------------------------------
__global__ __launch_bounds__(256) void attn_k()
{
    __shared__ float sQ [32][68];  // [row][d], pre-scaled
    __shared__ float sKT[64][33];  // [d][kcol] transposed, conflict-free S reads
    __shared__ float sV [32][68];  // [krow][d]
    __shared__ float sS [32][33];  // [qrow][kcol] probabilities

    const int tid = threadIdx.x;
    const int bh  = blockIdx.y;              // 0..63
    const int q0  = blockIdx.x * 32;

    const float* __restrict__ Qp = g_q + (size_t)bh * SEQ * HDIM;
    const float* __restrict__ Kp = g_k + (size_t)bh * SEQ * HDIM;
    const float* __restrict__ Vp = g_v + (size_t)bh * SEQ * HDIM;

    // Load + scale Q tile (32x64)
    for (int i = tid; i < (32 * HDIM) / 4; i += 256) {
        const int e = i * 4;
        const int r = e >> 6;
        const int d = e & 63;
        float4 qv = *(const float4*)(Qp + (size_t)(q0 + r) * HDIM + d);
        qv.x *= QK_SCALE; qv.y *= QK_SCALE; qv.z *= QK_SCALE; qv.w *= QK_SCALE;
        *(float4*)&sQ[r][d] = qv;
    }

    const int row = tid >> 3;        // q-row 0..31
    const int cb4 = (tid & 7) * 4;   // S col base
    const int cb8 = (tid & 7) * 8;   // O col base

    float acc[8] = {0, 0, 0, 0, 0, 0, 0, 0};
    float mrow = -1e30f;
    float lrow = 0.0f;

    for (int kt = 0; kt < SEQ / 32; kt++) {
        __syncthreads();   // protect sKT/sV from previous iteration's readers
        for (int i = tid; i < (32 * HDIM) / 4; i += 256) {
            const int e = i * 4;
            const int r = e >> 6;
            const int d = e & 63;
            float4 kv = *(const float4*)(Kp + (size_t)(kt * 32 + r) * HDIM + d);
            sKT[d + 0][r] = kv.x;
            sKT[d + 1][r] = kv.y;
            sKT[d + 2][r] = kv.z;
            sKT[d + 3][r] = kv.w;
            float4 vv = *(const float4*)(Vp + (size_t)(kt * 32 + r) * HDIM + d);
            *(float4*)&sV[r][d] = vv;
        }
        __syncthreads();

        // S = (Q*scale) @ K^T : 4 columns per thread
        float s0 = 0.f, s1 = 0.f, s2 = 0.f, s3 = 0.f;
#pragma unroll 8
        for (int d = 0; d < HDIM; d++) {
            const float q = sQ[row][d];
            s0 += q * sKT[d][cb4 + 0];
            s1 += q * sKT[d][cb4 + 1];
            s2 += q * sKT[d][cb4 + 2];
            s3 += q * sKT[d][cb4 + 3];
        }

        // row-wise max across the 8 lanes of this row (lanes aligned to 8)
        float tmax = fmaxf(fmaxf(s0, s1), fmaxf(s2, s3));
        tmax = fmaxf(tmax, __shfl_xor_sync(0xffffffffu, tmax, 1));
        tmax = fmaxf(tmax, __shfl_xor_sync(0xffffffffu, tmax, 2));
        tmax = fmaxf(tmax, __shfl_xor_sync(0xffffffffu, tmax, 4));

        const float newm = fmaxf(mrow, tmax);
        const float corr = __expf(mrow - newm);
        const float p0 = __expf(s0 - newm);
        const float p1 = __expf(s1 - newm);
        const float p2 = __expf(s2 - newm);
        const float p3 = __expf(s3 - newm);
        sS[row][cb4 + 0] = p0;
        sS[row][cb4 + 1] = p1;
        sS[row][cb4 + 2] = p2;
        sS[row][cb4 + 3] = p3;

        float ts = p0 + p1 + p2 + p3;
        ts += __shfl_xor_sync(0xffffffffu, ts, 1);
        ts += __shfl_xor_sync(0xffffffffu, ts, 2);
        ts += __shfl_xor_sync(0xffffffffu, ts, 4);

        lrow = lrow * corr + ts;
        mrow = newm;
#pragma unroll
        for (int c = 0; c < 8; c++) acc[c] *= corr;

        __syncwarp();   // sS written and read within the same warp

        // O += P @ V (8 cols per thread, float4 smem reads w/ broadcast)
#pragma unroll 4
        for (int kk = 0; kk < 32; kk++) {
            const float p = sS[row][kk];
            const float4 va = *(const float4*)&sV[kk][cb8];
            const float4 vb = *(const float4*)&sV[kk][cb8 + 4];
            acc[0] += p * va.x; acc[1] += p * va.y;
            acc[2] += p * va.z; acc[3] += p * va.w;
            acc[4] += p * vb.x; acc[5] += p * vb.y;
            acc[6] += p * vb.z; acc[7] += p * vb.w;
        }
    }

    const float inv = 1.0f / lrow;
    const int b = bh >> 4;
    const int h = bh & 15;
    float* op = g_attn + ((size_t)(b * SEQ + q0 + row)) * DIMC + h * HDIM + cb8;
#pragma unroll
    for (int c = 0; c < 8; c++) op[c] = acc[c] * inv;
}

// ---------------------------------------------------------------------------
extern "C" void kernel_launch(void* const* d_in, const int* in_sizes, int n_in,
                              void* d_out, int out_size)
{
    const float* x      = (const float*)d_in[0];
    const float* w_qkv  = (const float*)d_in[1];
    const float* b_qkv  = (const float*)d_in[2];
    const float* w_proj = (const float*)d_in[3];
    const float* b_proj = (const float*)d_in[4];
    float* out = (float*)d_out;

    // 1) qkv = x @ w_qkv + b_qkv, scattered into g_q/g_k/g_v [bh][s][d]
    {
        dim3 grid(3 * DIMC / 64, MROWS / 64);   // (48, 128)
        sgemm_k<0><<<grid, 256>>>(x, w_qkv, b_qkv, nullptr, DIMC, 3 * DIMC);
    }
    // 2) attention -> g_attn [b][s][h*64+d]
    {
        dim3 grid(SEQ / 32, BATCH * NHEAD);     // (64, 64)
        attn_k<<<grid, 256>>>();
    }
    // 3) out = g_attn @ w_proj + b_proj
    {
        dim3 grid(DIMC / 64, MROWS / 64);       // (16, 128)
        sgemm_k<1><<<grid, 256>>>(nullptr, w_proj, b_proj, out, DIMC, DIMC);
    }
}

// round 3
// speedup vs baseline: 1.9432x; 1.9432x over previous
#include <cuda_runtime.h>
#include <math.h>

// Problem constants
#define BATCH 4
#define SEQ   2048
#define DIMC  1024
#define NHEAD 16
#define HDIM  64
#define MROWS (BATCH * SEQ)      // 8192
#define QK_SCALE 0.125f          // 64^-0.5

// Scratch (device globals — allocation-free per harness rules)
__device__ float g_q[(size_t)BATCH * NHEAD * SEQ * HDIM];
__device__ float g_k[(size_t)BATCH * NHEAD * SEQ * HDIM];
__device__ float g_v[(size_t)BATCH * NHEAD * SEQ * HDIM];
__device__ float g_attn[(size_t)MROWS * DIMC];

// ---------------------------------------------------------------------------
// Tiled SGEMM: C[M,N] = A[M,K] @ B[K,N] + bias[N]
// 128x128 block tile, K-tile 16, 256 threads, 8x8 per-thread microtile.
// MODE 0: epilogue scatters into g_q/g_k/g_v with [b*H+h][s][d] layout.
// MODE 1: A is g_attn (ignores A param), plain row-major store to C.
// ---------------------------------------------------------------------------
template <int MODE>
__global__ __launch_bounds__(256) void sgemm_k(
    const float* __restrict__ A, const float* __restrict__ B,
    const float* __restrict__ bias, float* __restrict__ C,
    int K, int Ncols)
{
    __shared__ float As[16][132];   // [k][m] transposed, padded
    __shared__ float Bs[16][132];   // [k][n], padded

    const float* __restrict__ Ap = (MODE == 0) ? A : g_attn;

    const int tid = threadIdx.x;
    const int m0 = blockIdx.y * 128;
    const int n0 = blockIdx.x * 128;
    const int ty = tid >> 4;       // 0..15 -> 8 rows each
    const int tx = tid & 15;       // 0..15 -> 8 cols each

    float acc[8][8] = {};

    for (int k0 = 0; k0 < K; k0 += 16) {
        // Load A tile 128x16 (transposed into As[k][m]); 2 float4 per thread
#pragma unroll
        for (int i = 0; i < 2; i++) {
            const int idx  = tid * 2 + i;          // 0..511
            const int arow = idx >> 2;             // 0..127
            const int aseg = idx & 3;              // 0..3 (k chunks of 4)
            float4 av = *(const float4*)(Ap + (size_t)(m0 + arow) * K + k0 + aseg * 4);
            As[aseg * 4 + 0][arow] = av.x;
            As[aseg * 4 + 1][arow] = av.y;
            As[aseg * 4 + 2][arow] = av.z;
            As[aseg * 4 + 3][arow] = av.w;
        }
        // Load B tile 16x128; 2 float4 per thread
#pragma unroll
        for (int i = 0; i < 2; i++) {
            const int idx  = tid * 2 + i;          // 0..511
            const int brow = idx >> 5;             // 0..15
            const int bc4  = idx & 31;             // 0..31
            float4 bv = *(const float4*)(B + (size_t)(k0 + brow) * Ncols + n0 + bc4 * 4);
            *(float4*)&Bs[brow][bc4 * 4] = bv;
        }
        __syncthreads();

#pragma unroll
        for (int kk = 0; kk < 16; kk++) {
            float4 a0 = *(const float4*)&As[kk][ty * 8];
            float4 a1 = *(const float4*)&As[kk][ty * 8 + 4];
            float4 b0 = *(const float4*)&Bs[kk][tx * 8];
            float4 b1 = *(const float4*)&Bs[kk][tx * 8 + 4];
            float ar[8] = {a0.x, a0.y, a0.z, a0.w, a1.x, a1.y, a1.z, a1.w};
            float br[8] = {b0.x, b0.y, b0.z, b0.w, b1.x, b1.y, b1.z, b1.w};
#pragma unroll
            for (int i = 0; i < 8; i++)
#pragma unroll
                for (int j = 0; j < 8; j++)
                    acc[i][j] += ar[i] * br[j];
        }
        __syncthreads();
    }

    // Epilogue
    const int nb = n0 + tx * 8;                 // col base, multiple of 8
    float4 bia0 = *(const float4*)(bias + nb);
    float4 bia1 = *(const float4*)(bias + nb + 4);
#pragma unroll
    for (int i = 0; i < 8; i++) {
        const int m = m0 + ty * 8 + i;
        float4 v0 = {acc[i][0] + bia0.x, acc[i][1] + bia0.y,
                     acc[i][2] + bia0.z, acc[i][3] + bia0.w};
        float4 v1 = {acc[i][4] + bia1.x, acc[i][5] + bia1.y,
                     acc[i][6] + bia1.z, acc[i][7] + bia1.w};
        if (MODE == 0) {
            // nb..nb+7 stays within one (which, head) since 8 | 64
            const int which = nb >> 10;          // / 1024
            const int h     = (nb & 1023) >> 6;  // / 64
            const int d     = nb & 63;
            const int b     = m >> 11;           // / 2048
            const int s     = m & 2047;
            float* dst = (which == 0) ? g_q : (which == 1) ? g_k : g_v;
            float* p = dst + (((size_t)(b * NHEAD + h)) * SEQ + s) * HDIM + d;
            *(float4*)p = v0;
            *(float4*)(p + 4) = v1;
        } else {
            float* p = C + (size_t)m * Ncols + nb;
            *(float4*)p = v0;
            *(float4*)(p + 4) = v1;
        }
    }
}

// ---------------------------------------------------------------------------
// Flash-style attention, register-blocked.
// Block: 256 threads = 16(ty) x 16(tx). Q tile 64 rows, K/V tile 32 rows.
// S microtile: 4 rows (ty) x 2 cols (tx). O microtile: 4 rows x 4 cols.
// sP written/read within the same ty half-warp group -> __syncwarp only.
// Writes g_attn in [b][s][h*64+d] layout (ready for proj GEMM).
// ---------------------------------------------------------------------------
__global__ __launch_bounds__(256) void attn_k()
{
    __shared__ float sQ[64][68];   // [qrow][d], pre-scaled
    __shared__ float sK[32][68];   // [krow][d]
    __shared__ float sV[32][68];   // [krow][d]
    __shared__ float sP[64][36];   // [qrow][kcol] probabilities

    const int tid = threadIdx.x;
    const int bh  = blockIdx.y;              // 0..63
    const int q0  = blockIdx.x * 64;
    const int ty  = tid >> 4;                // 0..15 -> 4 q-rows
    const int tx  = tid & 15;                // 0..15

    const float* __restrict__ Qp = g_q + (size_t)bh * SEQ * HDIM;
    const float* __restrict__ Kp = g_k + (size_t)bh * SEQ * HDIM;
    const float* __restrict__ Vp = g_v + (size_t)bh * SEQ * HDIM;

    // Load + scale Q tile (64x64): 4 float4 per thread
#pragma unroll
    for (int i = 0; i < 4; i++) {
        const int idx = tid * 4 + i;         // 0..1023
        const int r = idx >> 4;              // /16 (16 float4 per row)
        const int d = (idx & 15) * 4;
        float4 qv = *(const float4*)(Qp + (size_t)(q0 + r) * HDIM + d);
        qv.x *= QK_SCALE; qv.y *= QK_SCALE; qv.z *= QK_SCALE; qv.w *= QK_SCALE;
        *(float4*)&sQ[r][d] = qv;
    }

    float oacc[4][4] = {};
    float mrow[4] = {-1e30f, -1e30f, -1e30f, -1e30f};
    float lrow[4] = {0.f, 0.f, 0.f, 0.f};

    for (int kt = 0; kt < SEQ / 32; kt++) {
        __syncthreads();   // protect sK/sV from previous iteration's readers
        // Load K/V tiles (32x64 each): 2 float4 per thread each
#pragma unroll
        for (int i = 0; i < 2; i++) {
            const int idx = tid * 2 + i;     // 0..511
            const int r = idx >> 4;
            const int d = (idx & 15) * 4;
            *(float4*)&sK[r][d] = *(const float4*)(Kp + (size_t)(kt * 32 + r) * HDIM + d);
            *(float4*)&sV[r][d] = *(const float4*)(Vp + (size_t)(kt * 32 + r) * HDIM + d);
        }
        __syncthreads();

        // S = Qs @ K^T : 4 rows x 2 cols per thread, float4 dots along d
        float s[4][2] = {};
#pragma unroll
        for (int d4 = 0; d4 < HDIM; d4 += 4) {
            float4 q4[4], k4[2];
#pragma unroll
            for (int i = 0; i < 4; i++) q4[i] = *(const float4*)&sQ[ty * 4 + i][d4];
#pragma unroll
            for (int j = 0; j < 2; j++) k4[j] = *(const float4*)&sK[tx * 2 + j][d4];
#pragma unroll
            for (int i = 0; i < 4; i++)
#pragma unroll
                for (int j = 0; j < 2; j++)
                    s[i][j] += q4[i].x * k4[j].x + q4[i].y * k4[j].y
                             + q4[i].z * k4[j].z + q4[i].w * k4[j].w;
        }

        // Online softmax per q-row (reduce across the 16 tx lanes of this ty)
        float corr[4];
#pragma unroll
        for (int i = 0; i < 4; i++) {
            float tmax = fmaxf(s[i][0], s[i][1]);
            tmax = fmaxf(tmax, __shfl_xor_sync(0xffffffffu, tmax, 1));
            tmax = fmaxf(tmax, __shfl_xor_sync(0xffffffffu, tmax, 2));
            tmax = fmaxf(tmax, __shfl_xor_sync(0xffffffffu, tmax, 4));
            tmax = fmaxf(tmax, __shfl_xor_sync(0xffffffffu, tmax, 8));
            const float newm = fmaxf(mrow[i], tmax);
            corr[i] = __expf(mrow[i] - newm);
            const float p0 = __expf(s[i][0] - newm);
            const float p1 = __expf(s[i][1] - newm);
            sP[ty * 4 + i][tx * 2 + 0] = p0;
            sP[ty * 4 + i][tx * 2 + 1] = p1;
            float ts = p0 + p1;
            ts += __shfl_xor_sync(0xffffffffu, ts, 1);
            ts += __shfl_xor_sync(0xffffffffu, ts, 2);
            ts += __shfl_xor_sync(0xffffffffu, ts, 4);
            ts += __shfl_xor_sync(0xffffffffu, ts, 8);
            lrow[i] = lrow[i] * corr[i] + ts;
            mrow[i] = newm;
        }
#pragma unroll
        for (int i = 0; i < 4; i++)
#pragma unroll
            for (int j = 0; j < 4; j++)
                oacc[i][j] *= corr[i];

        __syncwarp();   // sP rows for this ty group are warp-local

        // O += P @ V : 4 rows x 4 cols, float4 along kk
#pragma unroll
        for (int kk4 = 0; kk4 < 32; kk4 += 4) {
            float4 p4[4], v4[4];
#pragma unroll
            for (int i = 0; i < 4; i++) p4[i] = *(const float4*)&sP[ty * 4 + i][kk4];
#pragma unroll
            for (int r = 0; r < 4; r++) v4[r] = *(const float4*)&sV[kk4 + r][tx * 4];
#pragma unroll
            for (int i = 0; i < 4; i++) {
                oacc[i][0] += p4[i].x * v4[0].x + p4[i].y * v4[1].x
                            + p4[i].z * v4[2].x + p4[i].w * v4[3].x;
                oacc[i][1] += p4[i].x * v4[0].y + p4[i].y * v4[1].y
                            + p4[i].z * v4[2].y + p4[i].w * v4[3].y;
                oacc[i][2] += p4[i].x * v4[0].z + p4[i].y * v4[1].z
                            + p4[i].z * v4[2].z + p4[i].w * v4[3].z;
                oacc[i][3] += p4[i].x * v4[0].w + p4[i].y * v4[1].w
                            + p4[i].z * v4[2].w + p4[i].w * v4[3].w;
            }
        }
        __syncwarp();   // don't let next softmax overwrite sP early
    }

    // Epilogue: normalize and store to [b][s][h*64+d]
    const int b = bh >> 4;
    const int h = bh & 15;
#pragma unroll
    for (int i = 0; i < 4; i++) {
        const float inv = 1.0f / lrow[i];
        float4 ov = {oacc[i][0] * inv, oacc[i][1] * inv,
                     oacc[i][2] * inv, oacc[i][3] * inv};
        float* op = g_attn + ((size_t)(b * SEQ + q0 + ty * 4 + i)) * DIMC
                  + h * HDIM + tx * 4;
        *(float4*)op = ov;
    }
}

// ---------------------------------------------------------------------------
extern "C" void kernel_launch(void* const* d_in, const int* in_sizes, int n_in,
                              void* d_out, int out_size)
{
    const float* x      = (const float*)d_in[0];
    const float* w_qkv  = (const float*)d_in[1];
    const float* b_qkv  = (const float*)d_in[2];
    const float* w_proj = (const float*)d_in[3];
    const float* b_proj = (const float*)d_in[4];
    float* out = (float*)d_out;

    // 1) qkv = x @ w_qkv + b_qkv, scattered into g_q/g_k/g_v [bh][s][d]
    {
        dim3 grid(3 * DIMC / 128, MROWS / 128);   // (24, 64)
        sgemm_k<0><<<grid, 256>>>(x, w_qkv, b_qkv, nullptr, DIMC, 3 * DIMC);
    }
    // 2) attention -> g_attn [b][s][h*64+d]
    {
        dim3 grid(SEQ / 64, BATCH * NHEAD);       // (32, 64)
        attn_k<<<grid, 256>>>();
    }
    // 3) out = g_attn @ w_proj + b_proj
    {
        dim3 grid(DIMC / 128, MROWS / 128);       // (8, 64)
        sgemm_k<1><<<grid, 256>>>(nullptr, w_proj, b_proj, out, DIMC, DIMC);
    }
}

// round 11
// speedup vs baseline: 1.9522x; 1.0046x over previous
#include <cuda_runtime.h>
#include <math.h>

// Problem constants
#define BATCH 4
#define SEQ   2048
#define DIMC  1024
#define NHEAD 16
#define HDIM  64
#define MROWS (BATCH * SEQ)      // 8192
#define QK_SCALE 0.125f          // 64^-0.5

// Scratch (device globals — allocation-free per harness rules)
__device__ float g_q[(size_t)BATCH * NHEAD * SEQ * HDIM];
__device__ float g_k[(size_t)BATCH * NHEAD * SEQ * HDIM];
__device__ float g_v[(size_t)BATCH * NHEAD * SEQ * HDIM];
__device__ float g_attn[(size_t)MROWS * DIMC];

// ---------------- packed f32x2 helpers (sm_100+ PTX, plain target) ----------
typedef unsigned long long u64;
__device__ __forceinline__ void fma2(u64& d, u64 a, u64 b) {
    asm("fma.rn.f32x2 %0, %1, %2, %0;" : "+l"(d) : "l"(a), "l"(b));
}
__device__ __forceinline__ void mul2(u64& d, u64 a) {
    asm("mul.rn.f32x2 %0, %0, %1;" : "+l"(d) : "l"(a));
}
__device__ __forceinline__ u64 pack2(float x, float y) {
    u64 r;
    asm("mov.b64 %0, {%1, %2};" : "=l"(r) : "f"(x), "f"(y));
    return r;
}
__device__ __forceinline__ float2 unpack2(u64 v) {
    float2 r;
    asm("mov.b64 {%0, %1}, %2;" : "=f"(r.x), "=f"(r.y) : "l"(v));
    return r;
}

// ---------------------------------------------------------------------------
// Tiled SGEMM: C[M,N] = A[M,K] @ B[K,N] + bias[N]
// 128x128 block tile, K-tile 16, 256 threads, 8x8 per-thread microtile,
// inner product on packed f32x2 (FFMA2).
// MODE 0: epilogue scatters into g_q/g_k/g_v with [b*H+h][s][d] layout.
// MODE 1: A is g_attn (ignores A param), plain row-major store to C.
// ---------------------------------------------------------------------------
template <int MODE>
__global__ __launch_bounds__(256) void sgemm_k(
    const float* __restrict__ A, const float* __restrict__ B,
    const float* __restrict__ bias, float* __restrict__ C,
    int K, int Ncols)
{
    __shared__ float As[16][132];   // [k][m] transposed, padded (528B rows, 16B-mult)
    __shared__ float Bs[16][132];   // [k][n], padded

    const float* __restrict__ Ap = (MODE == 0) ? A : g_attn;

    const int tid = threadIdx.x;
    const int m0 = blockIdx.y * 128;
    const int n0 = blockIdx.x * 128;
    const int ty = tid >> 4;       // 0..15 -> 8 rows each
    const int tx = tid & 15;       // 0..15 -> 8 cols each

    u64 acc2[8][4] = {};           // 8 rows x 4 col-pairs

    for (int k0 = 0; k0 < K; k0 += 16) {
        // Load A tile 128x16 (transposed into As[k][m]); 2 float4 per thread
#pragma unroll
        for (int i = 0; i < 2; i++) {
            const int idx  = tid * 2 + i;          // 0..511
            const int arow = idx >> 2;             // 0..127
            const int aseg = idx & 3;              // 0..3 (k chunks of 4)
            float4 av = *(const float4*)(Ap + (size_t)(m0 + arow) * K + k0 + aseg * 4);
            As[aseg * 4 + 0][arow] = av.x;
            As[aseg * 4 + 1][arow] = av.y;
            As[aseg * 4 + 2][arow] = av.z;
            As[aseg * 4 + 3][arow] = av.w;
        }
        // Load B tile 16x128; 2 float4 per thread
#pragma unroll
        for (int i = 0; i < 2; i++) {
            const int idx  = tid * 2 + i;          // 0..511
            const int brow = idx >> 5;             // 0..15
            const int bc4  = idx & 31;             // 0..31
            float4 bv = *(const float4*)(B + (size_t)(k0 + brow) * Ncols + n0 + bc4 * 4);
            *(float4*)&Bs[brow][bc4 * 4] = bv;
        }
        __syncthreads();

#pragma unroll
        for (int kk = 0; kk < 16; kk++) {
            float4 a0 = *(const float4*)&As[kk][ty * 8];
            float4 a1 = *(const float4*)&As[kk][ty * 8 + 4];
            float4 b0 = *(const float4*)&Bs[kk][tx * 8];
            float4 b1 = *(const float4*)&Bs[kk][tx * 8 + 4];
            u64 bp[4] = {pack2(b0.x, b0.y), pack2(b0.z, b0.w),
                         pack2(b1.x, b1.y), pack2(b1.z, b1.w)};
            float ar[8] = {a0.x, a0.y, a0.z, a0.w, a1.x, a1.y, a1.z, a1.w};
#pragma unroll
            for (int i = 0; i < 8; i++) {
                u64 ad = pack2(ar[i], ar[i]);
#pragma unroll
                for (int j = 0; j < 4; j++)
                    fma2(acc2[i][j], ad, bp[j]);
            }
        }
        __syncthreads();
    }

    // Epilogue
    const int nb = n0 + tx * 8;                 // col base, multiple of 8
    float4 bia0 = *(const float4*)(bias + nb);
    float4 bia1 = *(const float4*)(bias + nb + 4);
#pragma unroll
    for (int i = 0; i < 8; i++) {
        const int m = m0 + ty * 8 + i;
        float2 c0 = unpack2(acc2[i][0]);
        float2 c1 = unpack2(acc2[i][1]);
        float2 c2 = unpack2(acc2[i][2]);
        float2 c3 = unpack2(acc2[i][3]);
        float4 v0 = {c0.x + bia0.x, c0.y + bia0.y, c1.x + bia0.z, c1.y + bia0.w};
        float4 v1 = {c2.x + bia1.x, c2.y + bia1.y, c3.x + bia1.z, c3.y + bia1.w};
        if (MODE == 0) {
            // nb..nb+7 stays within one (which, head) since 8 | 64
            const int which = nb >> 10;          // / 1024
            const int h     = (nb & 1023) >> 6;  // / 64
            const int d     = nb & 63;
            const int b     = m >> 11;           // / 2048
            const int s     = m & 2047;
            float* dst = (which == 0) ? g_q : (which == 1) ? g_k : g_v;
            float* p = dst + (((size_t)(b * NHEAD + h)) * SEQ + s) * HDIM + d;
            *(float4*)p = v0;
            *(float4*)(p + 4) = v1;
        } else {
            float* p = C + (size_t)m * Ncols + nb;
            *(float4*)p = v0;
            *(float4*)(p + 4) = v1;
        }
    }
}

// ---------------------------------------------------------------------------
// Flash-style attention, register-blocked, f32x2 inner products.
// Block: 256 threads = 16(ty) x 16(tx). Q tile 64 rows, K/V tile 32 rows.
// S microtile: 4 rows (ty) x 2 cols (tx). O microtile: 4 rows x 4 cols.
// sP written/read within the same ty half-warp group -> __syncwarp only.
// Writes g_attn in [b][s][h*64+d] layout (ready for proj GEMM).
// ---------------------------------------------------------------------------
__global__ __launch_bounds__(256) void attn_k()
{
    __shared__ float sQ[64][68];   // [qrow][d], pre-scaled (272B rows, 16B-mult)
    __shared__ float sK[32][68];   // [krow][d]
    __shared__ float sV[32][68];   // [krow][d]
    __shared__ float sP[64][36];   // [qrow][kcol] probabilities

    const int tid = threadIdx.x;
    const int bh  = blockIdx.y;              // 0..63
    const int q0  = blockIdx.x * 64;
    const int ty  = tid >> 4;                // 0..15 -> 4 q-rows
    const int tx  = tid & 15;                // 0..15

    const float* __restrict__ Qp = g_q + (size_t)bh * SEQ * HDIM;
    const float* __restrict__ Kp = g_k + (size_t)bh * SEQ * HDIM;
    const float* __restrict__ Vp = g_v + (size_t)bh * SEQ * HDIM;

    // Load + scale Q tile (64x64): 4 float4 per thread
#pragma unroll
    for (int i = 0; i < 4; i++) {
        const int idx = tid * 4 + i;         // 0..1023
        const int r = idx >> 4;              // /16 (16 float4 per row)
        const int d = (idx & 15) * 4;
        float4 qv = *(const float4*)(Qp + (size_t)(q0 + r) * HDIM + d);
        qv.x *= QK_SCALE; qv.y *= QK_SCALE; qv.z *= QK_SCALE; qv.w *= QK_SCALE;
        *(float4*)&sQ[r][d] = qv;
    }

    u64 o2[4][2] = {};                       // 4 rows x 2 col-pairs... x2 = 4 cols? no:
    // 4 rows x 4 cols -> 4 rows x 2 pairs
    float mrow[4] = {-1e30f, -1e30f, -1e30f, -1e30f};
    float lrow[4] = {0.f, 0.f, 0.f, 0.f};

    for (int kt = 0; kt < SEQ / 32; kt++) {
        __syncthreads();   // protect sK/sV from previous iteration's readers
        // Load K/V tiles (32x64 each): 2 float4 per thread each
#pragma unroll
        for (int i = 0; i < 2; i++) {
            const int idx = tid * 2 + i;     // 0..511
            const int r = idx >> 4;
            const int d = (idx & 15) * 4;
            *(float4*)&sK[r][d] = *(const float4*)(Kp + (size_t)(kt * 32 + r) * HDIM + d);
            *(float4*)&sV[r][d] = *(const float4*)(Vp + (size_t)(kt * 32 + r) * HDIM + d);
        }
        __syncthreads();

        // S = Qs @ K^T : 4 rows x 2 cols per thread, packed pairs along d
        u64 s2[4][2] = {};
#pragma unroll
        for (int d4 = 0; d4 < HDIM; d4 += 4) {
            u64 qp[4][2], kp[2][2];
#pragma unroll
            for (int i = 0; i < 4; i++) {
                float4 q4 = *(const float4*)&sQ[ty * 4 + i][d4];
                qp[i][0] = pack2(q4.x, q4.y);
                qp[i][1] = pack2(q4.z, q4.w);
            }
#pragma unroll
            for (int j = 0; j < 2; j++) {
                float4 k4 = *(const float4*)&sK[tx * 2 + j][d4];
                kp[j][0] = pack2(k4.x, k4.y);
                kp[j][1] = pack2(k4.z, k4.w);
            }
#pragma unroll
            for (int i = 0; i < 4; i++)
#pragma unroll
                for (int j = 0; j < 2; j++) {
                    fma2(s2[i][j], qp[i][0], kp[j][0]);
                    fma2(s2[i][j], qp[i][1], kp[j][1]);
                }
        }
        float s[4][2];
#pragma unroll
        for (int i = 0; i < 4; i++)
#pragma unroll
            for (int j = 0; j < 2; j++) {
                float2 h = unpack2(s2[i][j]);
                s[i][j] = h.x + h.y;
            }

        // Online softmax per q-row (reduce across the 16 tx lanes of this ty)
        float corr[4];
#pragma unroll
        for (int i = 0; i < 4; i++) {
            float tmax = fmaxf(s[i][0], s[i][1]);
            tmax = fmaxf(tmax, __shfl_xor_sync(0xffffffffu, tmax, 1));
            tmax = fmaxf(tmax, __shfl_xor_sync(0xffffffffu, tmax, 2));
            tmax = fmaxf(tmax, __shfl_xor_sync(0xffffffffu, tmax, 4));
            tmax = fmaxf(tmax, __shfl_xor_sync(0xffffffffu, tmax, 8));
            const float newm = fmaxf(mrow[i], tmax);
            corr[i] = __expf(mrow[i] - newm);
            const float p0 = __expf(s[i][0] - newm);
            const float p1 = __expf(s[i][1] - newm);
            sP[ty * 4 + i][tx * 2 + 0] = p0;
            sP[ty * 4 + i][tx * 2 + 1] = p1;
            float ts = p0 + p1;
            ts += __shfl_xor_sync(0xffffffffu, ts, 1);
            ts += __shfl_xor_sync(0xffffffffu, ts, 2);
            ts += __shfl_xor_sync(0xffffffffu, ts, 4);
            ts += __shfl_xor_sync(0xffffffffu, ts, 8);
            lrow[i] = lrow[i] * corr[i] + ts;
            mrow[i] = newm;
        }
#pragma unroll
        for (int i = 0; i < 4; i++) {
            u64 cd = pack2(corr[i], corr[i]);
            mul2(o2[i][0], cd);
            mul2(o2[i][1], cd);
        }

        __syncwarp();   // sP rows for this ty group are warp-local

        // O += P @ V : 4 rows x 4 cols (2 pairs), scalar p dup, packed v
#pragma unroll 4
        for (int kk = 0; kk < 32; kk++) {
            float4 v4 = *(const float4*)&sV[kk][tx * 4];
            u64 vp0 = pack2(v4.x, v4.y);
            u64 vp1 = pack2(v4.z, v4.w);
#pragma unroll
            for (int i = 0; i < 4; i++) {
                const float p = sP[ty * 4 + i][kk];
                u64 pd = pack2(p, p);
                fma2(o2[i][0], pd, vp0);
                fma2(o2[i][1], pd, vp1);
            }
        }
        __syncwarp();   // don't let next softmax overwrite sP early
    }

    // Epilogue: normalize and store to [b][s][h*64+d]
    const int b = bh >> 4;
    const int h = bh & 15;
#pragma unroll
    for (int i = 0; i < 4; i++) {
        const float inv = 1.0f / lrow[i];
        float2 c0 = unpack2(o2[i][0]);
        float2 c1 = unpack2(o2[i][1]);
        float4 ov = {c0.x * inv, c0.y * inv, c1.x * inv, c1.y * inv};
        float* op = g_attn + ((size_t)(b * SEQ + q0 + ty * 4 + i)) * DIMC
                  + h * HDIM + tx * 4;
        *(float4*)op = ov;
    }
}

// ---------------------------------------------------------------------------
extern "C" void kernel_launch(void* const* d_in, const int* in_sizes, int n_in,
                              void* d_out, int out_size)
{
    const float* x      = (const float*)d_in[0];
    const float* w_qkv  = (const float*)d_in[1];
    const float* b_qkv  = (const float*)d_in[2];
    const float* w_proj = (const float*)d_in[3];
    const float* b_proj = (const float*)d_in[4];
    float* out = (float*)d_out;

    // 1) qkv = x @ w_qkv + b_qkv, scattered into g_q/g_k/g_v [bh][s][d]
    {
        dim3 grid(3 * DIMC / 128, MROWS / 128);   // (24, 64)
        sgemm_k<0><<<grid, 256>>>(x, w_qkv, b_qkv, nullptr, DIMC, 3 * DIMC);
    }
    // 2) attention -> g_attn [b][s][h*64+d]
    {
        dim3 grid(SEQ / 64, BATCH * NHEAD);       // (32, 64)
        attn_k<<<grid, 256>>>();
    }
    // 3) out = g_attn @ w_proj + b_proj
    {
        dim3 grid(DIMC / 128, MROWS / 128);       // (8, 64)
        sgemm_k<1><<<grid, 256>>>(nullptr, w_proj, b_proj, out, DIMC, DIMC);
    }
}

// round 12
// speedup vs baseline: 2.3292x; 1.1931x over previous
#include <cuda_runtime.h>
#include <math.h>

// Problem constants
#define BATCH 4
#define SEQ   2048
#define DIMC  1024
#define NHEAD 16
#define HDIM  64
#define MROWS (BATCH * SEQ)      // 8192
#define QK_SCALE 0.125f          // 64^-0.5

// Scratch (device globals — allocation-free per harness rules)
__device__ float g_q[(size_t)BATCH * NHEAD * SEQ * HDIM];
__device__ float g_k[(size_t)BATCH * NHEAD * SEQ * HDIM];
__device__ float g_v[(size_t)BATCH * NHEAD * SEQ * HDIM];
__device__ float g_attn[(size_t)MROWS * DIMC];

// ---------------- packed f32x2 helpers (sm_100+ PTX, plain target) ----------
typedef unsigned long long u64;
__device__ __forceinline__ void fma2(u64& d, u64 a, u64 b) {
    asm("fma.rn.f32x2 %0, %1, %2, %0;" : "+l"(d) : "l"(a), "l"(b));
}
__device__ __forceinline__ void mul2(u64& d, u64 a) {
    asm("mul.rn.f32x2 %0, %0, %1;" : "+l"(d) : "l"(a));
}
__device__ __forceinline__ u64 pack2(float x, float y) {
    u64 r;
    asm("mov.b64 %0, {%1, %2};" : "=l"(r) : "f"(x), "f"(y));
    return r;
}
__device__ __forceinline__ float2 unpack2(u64 v) {
    float2 r;
    asm("mov.b64 {%0, %1}, %2;" : "=f"(r.x), "=f"(r.y) : "l"(v));
    return r;
}

// ---------------------------------------------------------------------------
// Tiled SGEMM: C[M,N] = A[M,K] @ B[K,N] + bias[N]
// 128x128 block tile, K-tile 16, 256 threads, 8x8 per-thread microtile.
// B microtile = two float4 groups at cols tx*4 and 64+tx*4 (conflict-free,
// lane stride 4 words). A reads are half-warp broadcasts.
// MODE 0: epilogue scatters into g_q/g_k/g_v with [b*H+h][s][d] layout.
// MODE 1: A is g_attn (ignores A param), plain row-major store to C.
// ---------------------------------------------------------------------------
template <int MODE>
__global__ __launch_bounds__(256) void sgemm_k(
    const float* __restrict__ A, const float* __restrict__ B,
    const float* __restrict__ bias, float* __restrict__ C,
    int K, int Ncols)
{
    __shared__ float As[16][132];   // [k][m] transposed, padded
    __shared__ float Bs[16][132];   // [k][n], padded

    const float* __restrict__ Ap = (MODE == 0) ? A : g_attn;

    const int tid = threadIdx.x;
    const int m0 = blockIdx.y * 128;
    const int n0 = blockIdx.x * 128;
    const int ty = tid >> 4;       // 0..15 -> 8 rows each
    const int tx = tid & 15;       // 0..15 -> cols tx*4 and 64+tx*4

    u64 acc2[8][4] = {};           // 8 rows x (2 pairs group0, 2 pairs group1)

    for (int k0 = 0; k0 < K; k0 += 16) {
        // Load A tile 128x16 (transposed into As[k][m]); 2 float4 per thread
#pragma unroll
        for (int i = 0; i < 2; i++) {
            const int idx  = tid * 2 + i;          // 0..511
            const int arow = idx >> 2;             // 0..127
            const int aseg = idx & 3;              // 0..3 (k chunks of 4)
            float4 av = *(const float4*)(Ap + (size_t)(m0 + arow) * K + k0 + aseg * 4);
            As[aseg * 4 + 0][arow] = av.x;
            As[aseg * 4 + 1][arow] = av.y;
            As[aseg * 4 + 2][arow] = av.z;
            As[aseg * 4 + 3][arow] = av.w;
        }
        // Load B tile 16x128; 2 float4 per thread
#pragma unroll
        for (int i = 0; i < 2; i++) {
            const int idx  = tid * 2 + i;          // 0..511
            const int brow = idx >> 5;             // 0..15
            const int bc4  = idx & 31;             // 0..31
            float4 bv = *(const float4*)(B + (size_t)(k0 + brow) * Ncols + n0 + bc4 * 4);
            *(float4*)&Bs[brow][bc4 * 4] = bv;
        }
        __syncthreads();

#pragma unroll
        for (int kk = 0; kk < 16; kk++) {
            float4 a0 = *(const float4*)&As[kk][ty * 8];        // broadcast
            float4 a1 = *(const float4*)&As[kk][ty * 8 + 4];    // broadcast
            float4 b0 = *(const float4*)&Bs[kk][tx * 4];        // 2-phase
            float4 b1 = *(const float4*)&Bs[kk][64 + tx * 4];   // 2-phase
            u64 bp[4] = {pack2(b0.x, b0.y), pack2(b0.z, b0.w),
                         pack2(b1.x, b1.y), pack2(b1.z, b1.w)};
            float ar[8] = {a0.x, a0.y, a0.z, a0.w, a1.x, a1.y, a1.z, a1.w};
#pragma unroll
            for (int i = 0; i < 8; i++) {
                u64 ad = pack2(ar[i], ar[i]);
#pragma unroll
                for (int j = 0; j < 4; j++)
                    fma2(acc2[i][j], ad, bp[j]);
            }
        }
        __syncthreads();
    }

    // Epilogue: two 4-col groups per row
    const int nbs[2] = {n0 + tx * 4, n0 + 64 + tx * 4};
    float4 bia[2] = {*(const float4*)(bias + nbs[0]),
                     *(const float4*)(bias + nbs[1])};
#pragma unroll
    for (int i = 0; i < 8; i++) {
        const int m = m0 + ty * 8 + i;
#pragma unroll
        for (int g = 0; g < 2; g++) {
            float2 c0 = unpack2(acc2[i][g * 2 + 0]);
            float2 c1 = unpack2(acc2[i][g * 2 + 1]);
            float4 v = {c0.x + bia[g].x, c0.y + bia[g].y,
                        c1.x + bia[g].z, c1.y + bia[g].w};
            const int nb = nbs[g];
            if (MODE == 0) {
                // nb..nb+3 stays within one (which, head) since 4 | 64
                const int which = nb >> 10;          // / 1024
                const int h     = (nb & 1023) >> 6;  // / 64
                const int d     = nb & 63;
                const int b     = m >> 11;           // / 2048
                const int s     = m & 2047;
                float* dst = (which == 0) ? g_q : (which == 1) ? g_k : g_v;
                *(float4*)(dst + (((size_t)(b * NHEAD + h)) * SEQ + s) * HDIM + d) = v;
            } else {
                *(float4*)(C + (size_t)m * Ncols + nb) = v;
            }
        }
    }
}

// ---------------------------------------------------------------------------
// Flash-style attention, conflict-free smem layouts.
// Block: 256 threads = 16(ty) x 16(tx). Q tile 64 rows, K/V tile 32 rows.
// sQT[d][qrow] (stride 68): S-phase Q = ONE broadcast LDS.128 per d (4 rows).
// sKT[d][kcol] (stride 33): scalar reads, bank = d+2tx+j -> conflict-free.
// sP[qrow][kcol] (stride 36): write conflict-free, PV reads float2 broadcast.
// sV[krow][d] (stride 68): float4 reads, 2-phase optimal.
// Writes g_attn in [b][s][h*64+d] layout (ready for proj GEMM).
// ---------------------------------------------------------------------------
__global__ __launch_bounds__(256) void attn_k()
{
    __shared__ float sQT[64 * 68];   // [d][qrow] pre-scaled, 17408 B
    __shared__ float sKT[64 * 33];   // [d][kcol],             8448 B
    __shared__ float sV[32][68];     // [krow][d],             8704 B
    __shared__ float sP[64][36];     // [qrow][kcol],          9216 B

    const int tid = threadIdx.x;
    const int bh  = blockIdx.y;              // 0..63
    const int q0  = blockIdx.x * 64;
    const int ty  = tid >> 4;                // 0..15 -> 4 q-rows
    const int tx  = tid & 15;                // 0..15 -> 2 k-cols / 4 d-cols

    const float* __restrict__ Qp = g_q + (size_t)bh * SEQ * HDIM;
    const float* __restrict__ Kp = g_k + (size_t)bh * SEQ * HDIM;
    const float* __restrict__ Vp = g_v + (size_t)bh * SEQ * HDIM;

    // Load + scale Q tile (64x64) transposed into sQT[d][qrow]
#pragma unroll
    for (int i = 0; i < 4; i++) {
        const int idx = tid * 4 + i;         // 0..1023
        const int r = idx >> 4;              // 0..63
        const int d = (idx & 15) * 4;
        float4 qv = *(const float4*)(Qp + (size_t)(q0 + r) * HDIM + d);
        sQT[(d + 0) * 68 + r] = qv.x * QK_SCALE;
        sQT[(d + 1) * 68 + r] = qv.y * QK_SCALE;
        sQT[(d + 2) * 68 + r] = qv.z * QK_SCALE;
        sQT[(d + 3) * 68 + r] = qv.w * QK_SCALE;
    }

    u64 o2[4][2] = {};                       // 4 rows x 2 col-pairs (4 d-cols)
    float mrow[4] = {-1e30f, -1e30f, -1e30f, -1e30f};
    float lrow[4] = {0.f, 0.f, 0.f, 0.f};

    for (int kt = 0; kt < SEQ / 32; kt++) {
        __syncthreads();   // prior readers of sKT/sV done (also covers sQT init)
        // Load K (transposed -> sKT) and V (natural): 2 float4 per thread each
#pragma unroll
        for (int i = 0; i < 2; i++) {
            const int idx = tid * 2 + i;     // 0..511
            const int r = idx >> 4;          // 0..31
            const int d = (idx & 15) * 4;
            float4 kv = *(const float4*)(Kp + (size_t)(kt * 32 + r) * HDIM + d);
            sKT[(d + 0) * 33 + r] = kv.x;
            sKT[(d + 1) * 33 + r] = kv.y;
            sKT[(d + 2) * 33 + r] = kv.z;
            sKT[(d + 3) * 33 + r] = kv.w;
            *(float4*)&sV[r][d] = *(const float4*)(Vp + (size_t)(kt * 32 + r) * HDIM + d);
        }
        __syncthreads();

        // S = Qs @ K^T : 4 rows (ty) x 2 cols (tx) per thread
        u64 s2[4] = {};                      // pair = (col0, col1)
#pragma unroll 8
        for (int d = 0; d < HDIM; d++) {
            float4 q4 = *(const float4*)&sQT[d * 68 + ty * 4];   // broadcast
            u64 kp = pack2(sKT[d * 33 + tx * 2], sKT[d * 33 + tx * 2 + 1]);
            fma2(s2[0], pack2(q4.x, q4.x), kp);
            fma2(s2[1], pack2(q4.y, q4.y), kp);
            fma2(s2[2], pack2(q4.z, q4.z), kp);
            fma2(s2[3], pack2(q4.w, q4.w), kp);
        }
        float s[4][2];
#pragma unroll
        for (int i = 0; i < 4; i++) {
            float2 h = unpack2(s2[i]);
            s[i][0] = h.x; s[i][1] = h.y;
        }

        // Online softmax per q-row (reduce across the 16 tx lanes of this ty)
        float corr[4];
#pragma unroll
        for (int i = 0; i < 4; i++) {
            float tmax = fmaxf(s[i][0], s[i][1]);
            tmax = fmaxf(tmax, __shfl_xor_sync(0xffffffffu, tmax, 1));
            tmax = fmaxf(tmax, __shfl_xor_sync(0xffffffffu, tmax, 2));
            tmax = fmaxf(tmax, __shfl_xor_sync(0xffffffffu, tmax, 4));
            tmax = fmaxf(tmax, __shfl_xor_sync(0xffffffffu, tmax, 8));
            const float newm = fmaxf(mrow[i], tmax);
            corr[i] = __expf(mrow[i] - newm);
            const float p0 = __expf(s[i][0] - newm);
            const float p1 = __expf(s[i][1] - newm);
            sP[ty * 4 + i][tx * 2 + 0] = p0;
            sP[ty * 4 + i][tx * 2 + 1] = p1;
            float ts = p0 + p1;
            ts += __shfl_xor_sync(0xffffffffu, ts, 1);
            ts += __shfl_xor_sync(0xffffffffu, ts, 2);
            ts += __shfl_xor_sync(0xffffffffu, ts, 4);
            ts += __shfl_xor_sync(0xffffffffu, ts, 8);
            lrow[i] = lrow[i] * corr[i] + ts;
            mrow[i] = newm;
        }
#pragma unroll
        for (int i = 0; i < 4; i++) {
            u64 cd = pack2(corr[i], corr[i]);
            mul2(o2[i][0], cd);
            mul2(o2[i][1], cd);
        }

        __syncwarp();   // sP rows for this ty group are warp-local

        // O += P @ V : per k-pair, P float2 broadcast + 2 V float4
#pragma unroll 4
        for (int k2 = 0; k2 < 16; k2++) {
            float4 v0 = *(const float4*)&sV[k2 * 2 + 0][tx * 4];
            float4 v1 = *(const float4*)&sV[k2 * 2 + 1][tx * 4];
            u64 v0p0 = pack2(v0.x, v0.y), v0p1 = pack2(v0.z, v0.w);
            u64 v1p0 = pack2(v1.x, v1.y), v1p1 = pack2(v1.z, v1.w);
#pragma unroll
            for (int i = 0; i < 4; i++) {
                float2 p = *(const float2*)&sP[ty * 4 + i][k2 * 2];  // broadcast
                u64 pa = pack2(p.x, p.x), pb = pack2(p.y, p.y);
                fma2(o2[i][0], pa, v0p0);
                fma2(o2[i][1], pa, v0p1);
                fma2(o2[i][0], pb, v1p0);
                fma2(o2[i][1], pb, v1p1);
            }
        }
    }

    // Epilogue: normalize and store to [b][s][h*64+d]
    const int b = bh >> 4;
    const int h = bh & 15;
#pragma unroll
    for (int i = 0; i < 4; i++) {
        const float inv = 1.0f / lrow[i];
        float2 c0 = unpack2(o2[i][0]);
        float2 c1 = unpack2(o2[i][1]);
        float4 ov = {c0.x * inv, c0.y * inv, c1.x * inv, c1.y * inv};
        float* op = g_attn + ((size_t)(b * SEQ + q0 + ty * 4 + i)) * DIMC
                  + h * HDIM + tx * 4;
        *(float4*)op = ov;
    }
}

// ---------------------------------------------------------------------------
extern "C" void kernel_launch(void* const* d_in, const int* in_sizes, int n_in,
                              void* d_out, int out_size)
{
    const float* x      = (const float*)d_in[0];
    const float* w_qkv  = (const float*)d_in[1];
    const float* b_qkv  = (const float*)d_in[2];
    const float* w_proj = (const float*)d_in[3];
    const float* b_proj = (const float*)d_in[4];
    float* out = (float*)d_out;

    // 1) qkv = x @ w_qkv + b_qkv, scattered into g_q/g_k/g_v [bh][s][d]
    {
        dim3 grid(3 * DIMC / 128, MROWS / 128);   // (24, 64)
        sgemm_k<0><<<grid, 256>>>(x, w_qkv, b_qkv, nullptr, DIMC, 3 * DIMC);
    }
    // 2) attention -> g_attn [b][s][h*64+d]
    {
        dim3 grid(SEQ / 64, BATCH * NHEAD);       // (32, 64)
        attn_k<<<grid, 256>>>();
    }
    // 3) out = g_attn @ w_proj + b_proj
    {
        dim3 grid(DIMC / 128, MROWS / 128);       // (8, 64)
        sgemm_k<1><<<grid, 256>>>(nullptr, w_proj, b_proj, out, DIMC, DIMC);
    }
}